// round 1
// baseline (speedup 1.0000x reference)
#include <cuda_runtime.h>

#define N_NODES 8192
#define F_IN    128
#define F_HID   64
#define F_OUT   2
#define EPSV    1e-6f

// ---------------- scratch (no allocations allowed) ----------------
__device__ float g_d[N_NODES];                 // 1/sqrt(rowsum+eps)
__device__ float g_z1[N_NODES * F_HID];        // d .* (x @ W1)
__device__ float g_h [N_NODES * F_HID];        // relu(d .* (A @ z1) + b1)
__device__ float g_z2[N_NODES * F_OUT];        // d .* (h @ W2)

// ---------------- f32x2 helpers (Blackwell packed fp32) ----------------
__device__ __forceinline__ void ffma2(unsigned long long &d,
                                      unsigned long long a,
                                      unsigned long long b) {
    asm("fma.rn.f32x2 %0, %1, %2, %0;" : "+l"(d) : "l"(a), "l"(b));
}
__device__ __forceinline__ unsigned long long pack2(float x) {
    unsigned long long r;
    asm("mov.b64 %0, {%1, %1};" : "=l"(r) : "f"(x));
    return r;
}
__device__ __forceinline__ void unpack2(float &lo, float &hi, unsigned long long v) {
    asm("mov.b64 {%0, %1}, %2;" : "=f"(lo), "=f"(hi) : "l"(v));
}

// ---------------- Kernel 1: d[i] = rsqrt(rowsum(adj)+eps) ----------------
__global__ void rowsum_kernel(const float* __restrict__ adj) {
    int row = blockIdx.x;
    const float4* a4 = reinterpret_cast<const float4*>(adj + (size_t)row * N_NODES);
    int t = threadIdx.x;
    float s = 0.f;
#pragma unroll
    for (int i = 0; i < N_NODES / 4 / 256; i++) {     // 8 iters
        float4 v = __ldg(&a4[t + i * 256]);
        s += (v.x + v.y) + (v.z + v.w);
    }
#pragma unroll
    for (int o = 16; o; o >>= 1) s += __shfl_xor_sync(0xffffffffu, s, o);
    __shared__ float ws[8];
    if ((t & 31) == 0) ws[t >> 5] = s;
    __syncthreads();
    if (t == 0) {
        float v = 0.f;
#pragma unroll
        for (int w = 0; w < 8; w++) v += ws[w];
        g_d[row] = rsqrtf(v + EPSV);
    }
}

// ---------------- Kernel 2: z1 = d .* (x @ W1)  [8192x128 @ 128x64] ----------------
// block = 64 rows, 256 threads: thread = (row within block) x (16-col slab)
__global__ void xw1_kernel(const float* __restrict__ x, const float* __restrict__ W1) {
    __shared__ float sW[F_IN][F_HID];   // 32 KB
    int t = threadIdx.x;
    for (int i = t; i < F_IN * F_HID; i += 256) sW[i / F_HID][i % F_HID] = W1[i];
    __syncthreads();

    int row = blockIdx.x * 64 + (t >> 2);
    int c0  = (t & 3) * 16;
    const float* xr = x + (size_t)row * F_IN;
    float acc[16];
#pragma unroll
    for (int c = 0; c < 16; c++) acc[c] = 0.f;
    for (int k = 0; k < F_IN; k++) {
        float xv = __ldg(xr + k);
#pragma unroll
        for (int c = 0; c < 16; c++) acc[c] += xv * sW[k][c0 + c];
    }
    float dv = g_d[row];
    float* out = g_z1 + (size_t)row * F_HID + c0;
#pragma unroll
    for (int c = 0; c < 16; c++) out[c] = dv * acc[c];
}

// ---------------- Kernel 3: h = relu(d .* (A @ z1) + b1)  [the big one] ----------------
// GEMM 8192x8192 @ 8192x64. BM=64, BN=64(full), BK=32, 256 threads.
// thread tile: TM=4 rows x TN=4 cols, accumulated as f32x2 pairs.
#define BM 64
#define BK 32
#define NT (N_NODES / BK)     // 256 k-tiles

__global__ void agg1_kernel(const float* __restrict__ adj, const float* __restrict__ b1) {
    __shared__ __align__(16) float sA[BK][BM + 4];   // [k][row], stride 68 (16B-aligned reads)
    __shared__ __align__(16) float sB[BK][F_HID];    // [k][col]
    __shared__ float sb1[F_HID];

    int t  = threadIdx.x;
    int tx = t & 15;           // col group: c0 = tx*4
    int ty = t >> 4;           // row group: r0 = ty*4
    int blockRow = blockIdx.x * BM;

    if (t < F_HID) sb1[t] = b1[t];

    const float* Ablk = adj + (size_t)blockRow * N_NODES;

    // A-tile load mapping: idx -> (lr = idx>>3 row, q = idx&7 float4-in-row)
    int a_lr0 = t >> 3,        a_q0 = t & 7;
    int a_lr1 = (t + 256) >> 3, a_q1 = a_q0;  // (t+256)&7 == t&7
    // B-tile load mapping: idx -> (kr = idx>>4, q = idx&15)
    int b_kr0 = t >> 4,         b_q0 = t & 15;
    int b_kr1 = (t + 256) >> 4, b_q1 = b_q0;

    unsigned long long acc[4][2];
#pragma unroll
    for (int i = 0; i < 4; i++) { acc[i][0] = 0ull; acc[i][1] = 0ull; }

    // ---- load tile 0 into smem ----
    {
        float4 pa0 = __ldg(reinterpret_cast<const float4*>(Ablk + (size_t)a_lr0 * N_NODES + a_q0 * 4));
        float4 pa1 = __ldg(reinterpret_cast<const float4*>(Ablk + (size_t)a_lr1 * N_NODES + a_q1 * 4));
        float4 pb0 = *reinterpret_cast<const float4*>(g_z1 + (size_t)b_kr0 * F_HID + b_q0 * 4);
        float4 pb1 = *reinterpret_cast<const float4*>(g_z1 + (size_t)b_kr1 * F_HID + b_q1 * 4);
        sA[a_q0 * 4 + 0][a_lr0] = pa0.x; sA[a_q0 * 4 + 1][a_lr0] = pa0.y;
        sA[a_q0 * 4 + 2][a_lr0] = pa0.z; sA[a_q0 * 4 + 3][a_lr0] = pa0.w;
        sA[a_q1 * 4 + 0][a_lr1] = pa1.x; sA[a_q1 * 4 + 1][a_lr1] = pa1.y;
        sA[a_q1 * 4 + 2][a_lr1] = pa1.z; sA[a_q1 * 4 + 3][a_lr1] = pa1.w;
        *reinterpret_cast<float4*>(&sB[b_kr0][b_q0 * 4]) = pb0;
        *reinterpret_cast<float4*>(&sB[b_kr1][b_q1 * 4]) = pb1;
    }
    __syncthreads();

    for (int kt = 0; kt < NT; kt++) {
        float4 pa0, pa1, pb0, pb1;
        bool more = (kt + 1 < NT);
        if (more) {
            int kb = (kt + 1) * BK;
            pa0 = __ldg(reinterpret_cast<const float4*>(Ablk + (size_t)a_lr0 * N_NODES + kb + a_q0 * 4));
            pa1 = __ldg(reinterpret_cast<const float4*>(Ablk + (size_t)a_lr1 * N_NODES + kb + a_q1 * 4));
            pb0 = *reinterpret_cast<const float4*>(g_z1 + (size_t)(kb + b_kr0) * F_HID + b_q0 * 4);
            pb1 = *reinterpret_cast<const float4*>(g_z1 + (size_t)(kb + b_kr1) * F_HID + b_q1 * 4);
        }

#pragma unroll
        for (int k = 0; k < BK; k++) {
            float4 av = *reinterpret_cast<const float4*>(&sA[k][ty * 4]);
            const unsigned long long* b64 =
                reinterpret_cast<const unsigned long long*>(&sB[k][tx * 4]);
            unsigned long long b01 = b64[0];
            unsigned long long b23 = b64[1];
            unsigned long long a;
            a = pack2(av.x); ffma2(acc[0][0], a, b01); ffma2(acc[0][1], a, b23);
            a = pack2(av.y); ffma2(acc[1][0], a, b01); ffma2(acc[1][1], a, b23);
            a = pack2(av.z); ffma2(acc[2][0], a, b01); ffma2(acc[2][1], a, b23);
            a = pack2(av.w); ffma2(acc[3][0], a, b01); ffma2(acc[3][1], a, b23);
        }
        __syncthreads();
        if (more) {
            sA[a_q0 * 4 + 0][a_lr0] = pa0.x; sA[a_q0 * 4 + 1][a_lr0] = pa0.y;
            sA[a_q0 * 4 + 2][a_lr0] = pa0.z; sA[a_q0 * 4 + 3][a_lr0] = pa0.w;
            sA[a_q1 * 4 + 0][a_lr1] = pa1.x; sA[a_q1 * 4 + 1][a_lr1] = pa1.y;
            sA[a_q1 * 4 + 2][a_lr1] = pa1.z; sA[a_q1 * 4 + 3][a_lr1] = pa1.w;
            *reinterpret_cast<float4*>(&sB[b_kr0][b_q0 * 4]) = pb0;
            *reinterpret_cast<float4*>(&sB[b_kr1][b_q1 * 4]) = pb1;
        }
        __syncthreads();
    }

    // epilogue: scale by d, add b1, relu, store
    int r0 = blockRow + ty * 4;
    int c0 = tx * 4;
#pragma unroll
    for (int i = 0; i < 4; i++) {
        float dv = g_d[r0 + i];
        float s0, s1, s2, s3;
        unpack2(s0, s1, acc[i][0]);
        unpack2(s2, s3, acc[i][1]);
        float4 hv;
        hv.x = fmaxf(fmaf(dv, s0, sb1[c0 + 0]), 0.f);
        hv.y = fmaxf(fmaf(dv, s1, sb1[c0 + 1]), 0.f);
        hv.z = fmaxf(fmaf(dv, s2, sb1[c0 + 2]), 0.f);
        hv.w = fmaxf(fmaf(dv, s3, sb1[c0 + 3]), 0.f);
        *reinterpret_cast<float4*>(&g_h[(size_t)(r0 + i) * F_HID + c0]) = hv;
    }
}

// ---------------- Kernel 4: z2 = d .* (h @ W2)  [8192x64 @ 64x2] ----------------
__global__ void hw2_kernel(const float* __restrict__ W2) {
    __shared__ float sW[F_HID * F_OUT];
    int t = threadIdx.x;
    if (t < F_HID * F_OUT) sW[t] = W2[t];
    __syncthreads();
    int row = blockIdx.x * 256 + t;
    const float4* hr = reinterpret_cast<const float4*>(g_h + (size_t)row * F_HID);
    float a0 = 0.f, a1 = 0.f;
#pragma unroll
    for (int i = 0; i < F_HID / 4; i++) {
        float4 h = hr[i];
        a0 += h.x * sW[(4 * i + 0) * 2] + h.y * sW[(4 * i + 1) * 2]
            + h.z * sW[(4 * i + 2) * 2] + h.w * sW[(4 * i + 3) * 2];
        a1 += h.x * sW[(4 * i + 0) * 2 + 1] + h.y * sW[(4 * i + 1) * 2 + 1]
            + h.z * sW[(4 * i + 2) * 2 + 1] + h.w * sW[(4 * i + 3) * 2 + 1];
    }
    float dv = g_d[row];
    g_z2[2 * row + 0] = dv * a0;
    g_z2[2 * row + 1] = dv * a1;
}

// ---------------- Kernel 5: out = d .* (A @ z2) + b2 ----------------
// one block per row; z2 (64 KB) stays hot in L1/L2.
__global__ void agg2_kernel(const float* __restrict__ adj, const float* __restrict__ b2,
                            float* __restrict__ out) {
    int row = blockIdx.x;
    int t = threadIdx.x;
    const float4* a4 = reinterpret_cast<const float4*>(adj + (size_t)row * N_NODES);
    const float2* z2 = reinterpret_cast<const float2*>(g_z2);
    float a0 = 0.f, a1 = 0.f;
#pragma unroll
    for (int i = 0; i < N_NODES / 4 / 256; i++) {     // 8 iters
        int j = t + 256 * i;
        float4 v = __ldg(&a4[j]);
        float2 z0 = __ldg(&z2[4 * j + 0]);
        float2 z1 = __ldg(&z2[4 * j + 1]);
        float2 z2v = __ldg(&z2[4 * j + 2]);
        float2 z3 = __ldg(&z2[4 * j + 3]);
        a0 += v.x * z0.x + v.y * z1.x + v.z * z2v.x + v.w * z3.x;
        a1 += v.x * z0.y + v.y * z1.y + v.z * z2v.y + v.w * z3.y;
    }
#pragma unroll
    for (int o = 16; o; o >>= 1) {
        a0 += __shfl_xor_sync(0xffffffffu, a0, o);
        a1 += __shfl_xor_sync(0xffffffffu, a1, o);
    }
    __shared__ float red[16];
    if ((t & 31) == 0) { red[(t >> 5) * 2] = a0; red[(t >> 5) * 2 + 1] = a1; }
    __syncthreads();
    if (t == 0) {
        float s0 = 0.f, s1 = 0.f;
#pragma unroll
        for (int w = 0; w < 8; w++) { s0 += red[2 * w]; s1 += red[2 * w + 1]; }
        float dv = g_d[row];
        out[2 * row + 0] = fmaf(dv, s0, b2[0]);
        out[2 * row + 1] = fmaf(dv, s1, b2[1]);
    }
}

// ---------------- launch ----------------
extern "C" void kernel_launch(void* const* d_in, const int* in_sizes, int n_in,
                              void* d_out, int out_size) {
    const float* x   = (const float*)d_in[0];   // 8192x128
    const float* adj = (const float*)d_in[1];   // 8192x8192
    const float* W1  = (const float*)d_in[2];   // 128x64
    const float* b1  = (const float*)d_in[3];   // 64
    const float* W2  = (const float*)d_in[4];   // 64x2
    const float* b2  = (const float*)d_in[5];   // 2
    float* out = (float*)d_out;                 // 8192x2

    rowsum_kernel<<<N_NODES, 256>>>(adj);
    xw1_kernel<<<N_NODES / 64, 256>>>(x, W1);
    agg1_kernel<<<N_NODES / BM, 256>>>(adj, b1);
    hw2_kernel<<<N_NODES / 256, 256>>>(W2);
    agg2_kernel<<<N_NODES, 256>>>(adj, b2, out);
}

// round 3
// speedup vs baseline: 1.6129x; 1.6129x over previous
#include <cuda_runtime.h>
#include <cuda_bf16.h>
#include <cstdint>

#define N_NODES 8192
#define F_IN    128
#define F_HID   64
#define F_OUT   2
#define EPSV    1e-6f

// ---------------- scratch (no allocations allowed) ----------------
__device__ float g_d[N_NODES];                          // 1/sqrt(rowsum+eps)
__device__ __nv_bfloat16 g_z1hiT[F_HID * N_NODES];      // (d.*xW1)^T hi, [64][8192] K-major
__device__ __nv_bfloat16 g_z1loT[F_HID * N_NODES];      // (d.*xW1)^T lo
__device__ float g_part[2 * N_NODES * F_HID];           // split-K partials of A @ z1
__device__ float g_z2[N_NODES * F_OUT];                 // d .* (h @ W2)

// ================= helpers =================
__device__ __forceinline__ uint32_t smem_u32(const void* p) {
    uint32_t a;
    asm("{ .reg .u64 t; cvta.to.shared.u64 t, %1; cvt.u32.u64 %0, t; }" : "=r"(a) : "l"(p));
    return a;
}
// pack two fp32 -> bf16x2, f0 in low half (first k element), f1 in high half
__device__ __forceinline__ uint32_t pack_bf(float f0, float f1) {
    uint32_t r;
    asm("cvt.rn.bf16x2.f32 %0, %1, %2;" : "=r"(r) : "f"(f1), "f"(f0));
    return r;
}
__device__ __forceinline__ void ldsm_x4(uint32_t* r, uint32_t addr) {
    asm volatile("ldmatrix.sync.aligned.m8n8.x4.shared.b16 {%0,%1,%2,%3}, [%4];"
                 : "=r"(r[0]), "=r"(r[1]), "=r"(r[2]), "=r"(r[3]) : "r"(addr));
}
__device__ __forceinline__ void mma16816(float* d, const uint32_t* a,
                                         uint32_t b0, uint32_t b1) {
    asm volatile(
        "mma.sync.aligned.m16n8k16.row.col.f32.bf16.bf16.f32 "
        "{%0,%1,%2,%3}, {%4,%5,%6,%7}, {%8,%9}, {%0,%1,%2,%3};"
        : "+f"(d[0]), "+f"(d[1]), "+f"(d[2]), "+f"(d[3])
        : "r"(a[0]), "r"(a[1]), "r"(a[2]), "r"(a[3]), "r"(b0), "r"(b1));
}

// ---------------- Kernel 1: rowsum -> d ----------------
__global__ void rowsum_kernel(const float* __restrict__ adj) {
    int row = blockIdx.x;
    const float4* a4 = reinterpret_cast<const float4*>(adj + (size_t)row * N_NODES);
    int t = threadIdx.x;
    float s = 0.f;
#pragma unroll
    for (int i = 0; i < N_NODES / 4 / 256; i++) {
        float4 v = __ldg(&a4[t + i * 256]);
        s += (v.x + v.y) + (v.z + v.w);
    }
#pragma unroll
    for (int o = 16; o; o >>= 1) s += __shfl_xor_sync(0xffffffffu, s, o);
    __shared__ float ws[8];
    if ((t & 31) == 0) ws[t >> 5] = s;
    __syncthreads();
    if (t == 0) {
        float v = 0.f;
#pragma unroll
        for (int w = 0; w < 8; w++) v += ws[w];
        g_d[row] = rsqrtf(v + EPSV);
    }
}

// ---------------- Kernel 2: z1^T (bf16 hi/lo) = (d .* (x @ W1))^T ----------------
__global__ void xw1_kernel(const float* __restrict__ x, const float* __restrict__ W1) {
    __shared__ float sW[F_IN][F_HID];
    int t = threadIdx.x;
    for (int i = t; i < F_IN * F_HID; i += 256) sW[i / F_HID][i % F_HID] = W1[i];
    __syncthreads();

    int row = blockIdx.x * 64 + (t >> 2);
    int c0  = (t & 3) * 16;
    const float* xr = x + (size_t)row * F_IN;
    float acc[16];
#pragma unroll
    for (int c = 0; c < 16; c++) acc[c] = 0.f;
    for (int k = 0; k < F_IN; k++) {
        float xv = __ldg(xr + k);
#pragma unroll
        for (int c = 0; c < 16; c++) acc[c] += xv * sW[k][c0 + c];
    }
    float dv = g_d[row];
#pragma unroll
    for (int c = 0; c < 16; c++) {
        float z = dv * acc[c];
        __nv_bfloat16 hi = __float2bfloat16(z);
        float res = z - __bfloat162float(hi);
        __nv_bfloat16 lo = __float2bfloat16(res);
        g_z1hiT[(size_t)(c0 + c) * N_NODES + row] = hi;
        g_z1loT[(size_t)(c0 + c) * N_NODES + row] = lo;
    }
}

// ---------------- Kernel 3: HMMA split-K GEMM: part[s] = A[:, ks] @ z1[ks, :] ----------------
// BM=128 rows/CTA, BN=64 (full), KT=64, 256 threads (8 warps, 4x2 of 32x32 tiles).
// bf16 3-product split for fp32-grade accuracy. Double-buffered smem.
#define KT        64
#define K_SPLIT   (N_NODES / 2)         // 4096
#define NKT       (K_SPLIT / KT)        // 64
#define ROW_B     144                   // (KT+8) bf16 = 144 bytes per smem row
#define OFF_ALO   18432                 // 128*144
#define OFF_BHI   36864
#define OFF_BLO   46080                 // + 64*144
#define STAGE_B   55296
#define SMEM_SZ   (2 * STAGE_B)         // 110592

__global__ __launch_bounds__(256, 1)
void agg1_mma_kernel(const float* __restrict__ adj) {
    extern __shared__ __align__(1024) char smem[];
    uint32_t sbase = smem_u32(smem);
    int t = threadIdx.x;
    int wid = t >> 5, lane = t & 31;

    int mtile = blockIdx.x >> 1;
    int split = blockIdx.x & 1;
    int blockRow = mtile * 128;
    int kbase = split * K_SPLIT;

    int warpM = (wid & 3) * 32;         // 0,32,64,96
    int warpN = (wid >> 2) * 32;        // 0,32

    // lane-dependent ldmatrix offsets
    uint32_t aLane = (uint32_t)((lane & 15) * ROW_B + (lane >> 4) * 16);
    uint32_t bLane = (uint32_t)(((lane & 7) + ((lane >> 4) & 1) * 8) * ROW_B +
                                ((lane >> 3) & 1) * 16);
    uint32_t mrow0 = (uint32_t)(warpM * ROW_B);
    uint32_t mrow1 = (uint32_t)((warpM + 16) * ROW_B);
    uint32_t nrow0 = (uint32_t)(warpN * ROW_B);
    uint32_t nrow1 = (uint32_t)((warpN + 16) * ROW_B);

    // gmem staging mapping
    int a_r = t >> 1, a_half = t & 1;             // A: row, 32-float half
    int b_n = t >> 2, b_q = t & 3;                // B: n row, chunk
    const float* aRow = adj + (size_t)(blockRow + a_r) * N_NODES + kbase + a_half * 32;
    const __nv_bfloat16* bhRow = g_z1hiT + (size_t)b_n * N_NODES + kbase;
    const __nv_bfloat16* blRow = g_z1loT + (size_t)b_n * N_NODES + kbase;

    float4 aReg[8];
    float4 bhReg[2], blReg[2];

    float acc[2][4][4];
#pragma unroll
    for (int mi = 0; mi < 2; mi++)
#pragma unroll
        for (int bi = 0; bi < 4; bi++)
#pragma unroll
            for (int e = 0; e < 4; e++) acc[mi][bi][e] = 0.f;

    // helpers to load gmem tile into regs / store regs into smem stage
    auto ldg_tile = [&](int kt) {
        const float4* ap = reinterpret_cast<const float4*>(aRow + kt * KT);
#pragma unroll
        for (int i = 0; i < 8; i++) aReg[i] = __ldg(&ap[i]);
        const float4* bh = reinterpret_cast<const float4*>(bhRow + kt * KT);
        const float4* bl = reinterpret_cast<const float4*>(blRow + kt * KT);
        bhReg[0] = __ldg(&bh[b_q]);     bhReg[1] = __ldg(&bh[b_q + 4]);
        blReg[0] = __ldg(&bl[b_q]);     blReg[1] = __ldg(&bl[b_q + 4]);
    };
    auto sts_tile = [&](int stage) {
        char* st = smem + stage * STAGE_B;
        uint32_t arow = (uint32_t)(a_r * ROW_B + a_half * 64);
#pragma unroll
        for (int i = 0; i < 8; i++) {
            uint32_t h01 = pack_bf(aReg[i].x, aReg[i].y);
            uint32_t h23 = pack_bf(aReg[i].z, aReg[i].w);
            float r0 = aReg[i].x - __uint_as_float(h01 << 16);
            float r1 = aReg[i].y - __uint_as_float(h01 & 0xffff0000u);
            float r2 = aReg[i].z - __uint_as_float(h23 << 16);
            float r3 = aReg[i].w - __uint_as_float(h23 & 0xffff0000u);
            uint32_t l01 = pack_bf(r0, r1);
            uint32_t l23 = pack_bf(r2, r3);
            *reinterpret_cast<uint2*>(st + arow + i * 8) = make_uint2(h01, h23);
            *reinterpret_cast<uint2*>(st + OFF_ALO + arow + i * 8) = make_uint2(l01, l23);
        }
        uint32_t brow = (uint32_t)(b_n * ROW_B + b_q * 16);
        *reinterpret_cast<float4*>(st + OFF_BHI + brow)      = bhReg[0];
        *reinterpret_cast<float4*>(st + OFF_BHI + brow + 64) = bhReg[1];
        *reinterpret_cast<float4*>(st + OFF_BLO + brow)      = blReg[0];
        *reinterpret_cast<float4*>(st + OFF_BLO + brow + 64) = blReg[1];
    };

    // prologue
    ldg_tile(0);
    sts_tile(0);
    __syncthreads();

    for (int kt = 0; kt < NKT; kt++) {
        int s = kt & 1;
        bool more = (kt + 1 < NKT);
        if (more) ldg_tile(kt + 1);          // overlaps with MMA below

        uint32_t sa  = sbase + (uint32_t)(s * STAGE_B);
        uint32_t ahi = sa;
        uint32_t alo = sa + OFF_ALO;
        uint32_t bhi = sa + OFF_BHI;
        uint32_t blo = sa + OFF_BLO;

#pragma unroll
        for (int ks = 0; ks < 4; ks++) {
            uint32_t ko = (uint32_t)(ks * 32);
            uint32_t Ah[2][4], Al[2][4], Bh[8], Bl[8];
            ldsm_x4(Ah[0], ahi + mrow0 + aLane + ko);
            ldsm_x4(Ah[1], ahi + mrow1 + aLane + ko);
            ldsm_x4(Al[0], alo + mrow0 + aLane + ko);
            ldsm_x4(Al[1], alo + mrow1 + aLane + ko);
            ldsm_x4(Bh + 0, bhi + nrow0 + bLane + ko);
            ldsm_x4(Bh + 4, bhi + nrow1 + bLane + ko);
            ldsm_x4(Bl + 0, blo + nrow0 + bLane + ko);
            ldsm_x4(Bl + 4, blo + nrow1 + bLane + ko);
#pragma unroll
            for (int mi = 0; mi < 2; mi++) {
#pragma unroll
                for (int bi = 0; bi < 4; bi++) {
                    mma16816(acc[mi][bi], Ah[mi], Bh[bi * 2], Bh[bi * 2 + 1]);
                    mma16816(acc[mi][bi], Ah[mi], Bl[bi * 2], Bl[bi * 2 + 1]);
                    mma16816(acc[mi][bi], Al[mi], Bh[bi * 2], Bh[bi * 2 + 1]);
                }
            }
        }
        if (more) sts_tile(s ^ 1);           // stage s^1 free since iteration kt-1
        __syncthreads();
    }

    // epilogue: write split-K partials
    int g = lane >> 2, tig = lane & 3;
    float* base = g_part + (size_t)split * N_NODES * F_HID;
#pragma unroll
    for (int mi = 0; mi < 2; mi++) {
        int row = blockRow + warpM + mi * 16 + g;
#pragma unroll
        for (int bi = 0; bi < 4; bi++) {
            int col = warpN + bi * 8 + tig * 2;
            *reinterpret_cast<float2*>(base + (size_t)row * F_HID + col) =
                make_float2(acc[mi][bi][0], acc[mi][bi][1]);
            *reinterpret_cast<float2*>(base + (size_t)(row + 8) * F_HID + col) =
                make_float2(acc[mi][bi][2], acc[mi][bi][3]);
        }
    }
}

// ---------------- Kernel 4: h = relu(d.*(p0+p1)+b1); z2 = d .* (h @ W2) ----------------
__global__ void hw2_fused_kernel(const float* __restrict__ W2, const float* __restrict__ b1) {
    __shared__ float sW[F_HID * F_OUT];
    __shared__ float sb1[F_HID];
    int t = threadIdx.x;
    if (t < F_HID * F_OUT) sW[t] = W2[t];
    if (t < F_HID) sb1[t] = b1[t];
    __syncthreads();
    int row = blockIdx.x * 256 + t;
    float dv = g_d[row];
    const float4* p0 = reinterpret_cast<const float4*>(g_part + (size_t)row * F_HID);
    const float4* p1 = reinterpret_cast<const float4*>(g_part + ((size_t)N_NODES + row) * F_HID);
    float a0 = 0.f, a1 = 0.f;
#pragma unroll
    for (int i = 0; i < F_HID / 4; i++) {
        float4 u = __ldg(&p0[i]);
        float4 v = __ldg(&p1[i]);
        float h0 = fmaxf(fmaf(dv, u.x + v.x, sb1[4 * i + 0]), 0.f);
        float h1 = fmaxf(fmaf(dv, u.y + v.y, sb1[4 * i + 1]), 0.f);
        float h2 = fmaxf(fmaf(dv, u.z + v.z, sb1[4 * i + 2]), 0.f);
        float h3 = fmaxf(fmaf(dv, u.w + v.w, sb1[4 * i + 3]), 0.f);
        a0 += h0 * sW[(4 * i + 0) * 2] + h1 * sW[(4 * i + 1) * 2]
            + h2 * sW[(4 * i + 2) * 2] + h3 * sW[(4 * i + 3) * 2];
        a1 += h0 * sW[(4 * i + 0) * 2 + 1] + h1 * sW[(4 * i + 1) * 2 + 1]
            + h2 * sW[(4 * i + 2) * 2 + 1] + h3 * sW[(4 * i + 3) * 2 + 1];
    }
    g_z2[2 * row + 0] = dv * a0;
    g_z2[2 * row + 1] = dv * a1;
}

// ---------------- Kernel 5: out = d .* (A @ z2) + b2 ----------------
__global__ void agg2_kernel(const float* __restrict__ adj, const float* __restrict__ b2,
                            float* __restrict__ out) {
    int row = blockIdx.x;
    int t = threadIdx.x;
    const float4* a4 = reinterpret_cast<const float4*>(adj + (size_t)row * N_NODES);
    const float2* z2 = reinterpret_cast<const float2*>(g_z2);
    float a0 = 0.f, a1 = 0.f;
#pragma unroll
    for (int i = 0; i < N_NODES / 4 / 256; i++) {
        int j = t + 256 * i;
        float4 v = __ldg(&a4[j]);
        float2 z0 = __ldg(&z2[4 * j + 0]);
        float2 z1 = __ldg(&z2[4 * j + 1]);
        float2 zz = __ldg(&z2[4 * j + 2]);
        float2 z3 = __ldg(&z2[4 * j + 3]);
        a0 += v.x * z0.x + v.y * z1.x + v.z * zz.x + v.w * z3.x;
        a1 += v.x * z0.y + v.y * z1.y + v.z * zz.y + v.w * z3.y;
    }
#pragma unroll
    for (int o = 16; o; o >>= 1) {
        a0 += __shfl_xor_sync(0xffffffffu, a0, o);
        a1 += __shfl_xor_sync(0xffffffffu, a1, o);
    }
    __shared__ float red[16];
    if ((t & 31) == 0) { red[(t >> 5) * 2] = a0; red[(t >> 5) * 2 + 1] = a1; }
    __syncthreads();
    if (t == 0) {
        float s0 = 0.f, s1 = 0.f;
#pragma unroll
        for (int w = 0; w < 8; w++) { s0 += red[2 * w]; s1 += red[2 * w + 1]; }
        float dv = g_d[row];
        out[2 * row + 0] = fmaf(dv, s0, b2[0]);
        out[2 * row + 1] = fmaf(dv, s1, b2[1]);
    }
}

// ---------------- launch ----------------
extern "C" void kernel_launch(void* const* d_in, const int* in_sizes, int n_in,
                              void* d_out, int out_size) {
    const float* x   = (const float*)d_in[0];
    const float* adj = (const float*)d_in[1];
    const float* W1  = (const float*)d_in[2];
    const float* b1  = (const float*)d_in[3];
    const float* W2  = (const float*)d_in[4];
    const float* b2  = (const float*)d_in[5];
    float* out = (float*)d_out;

    cudaFuncSetAttribute(agg1_mma_kernel,
                         cudaFuncAttributeMaxDynamicSharedMemorySize, SMEM_SZ);

    rowsum_kernel<<<N_NODES, 256>>>(adj);
    xw1_kernel<<<N_NODES / 64, 256>>>(x, W1);
    agg1_mma_kernel<<<2 * (N_NODES / 128), 256, SMEM_SZ>>>(adj);
    hw2_fused_kernel<<<N_NODES / 256, 256>>>(W2, b1);
    agg2_kernel<<<N_NODES, 256>>>(adj, b2, out);
}

// round 7
// speedup vs baseline: 1.7585x; 1.0903x over previous
#include <cuda_runtime.h>
#include <cuda_bf16.h>
#include <cstdint>

#define N_NODES 8192
#define F_IN    128
#define F_HID   64
#define F_OUT   2
#define EPSV    1e-6f

// ---------------- scratch (no allocations allowed) ----------------
__device__ float g_d[N_NODES];                          // 1/sqrt(rowsum+eps)
__device__ __nv_bfloat16 g_z1hiT[F_HID * N_NODES];      // (d.*xW1)^T hi, [64][8192]
__device__ __nv_bfloat16 g_z1loT[F_HID * N_NODES];      // (d.*xW1)^T lo
__device__ float g_part[2 * N_NODES * F_HID];           // split-K partials of A @ z1
__device__ float g_z2[N_NODES * F_OUT];                 // d .* (h @ W2)

// ================= helpers =================
__device__ __forceinline__ uint32_t smem_u32(const void* p) {
    uint32_t a;
    asm("{ .reg .u64 t; cvta.to.shared.u64 t, %1; cvt.u32.u64 %0, t; }" : "=r"(a) : "l"(p));
    return a;
}
// pack two fp32 -> bf16x2, f0 in low half (first k element)
__device__ __forceinline__ uint32_t pack_bf(float f0, float f1) {
    uint32_t r;
    asm("cvt.rn.bf16x2.f32 %0, %1, %2;" : "=r"(r) : "f"(f1), "f"(f0));
    return r;
}
__device__ __forceinline__ void ldsm_x4(uint32_t* r, uint32_t addr) {
    asm volatile("ldmatrix.sync.aligned.m8n8.x4.shared.b16 {%0,%1,%2,%3}, [%4];"
                 : "=r"(r[0]), "=r"(r[1]), "=r"(r[2]), "=r"(r[3]) : "r"(addr));
}
__device__ __forceinline__ void mma16816(float* d, const uint32_t* a,
                                         uint32_t b0, uint32_t b1) {
    asm volatile(
        "mma.sync.aligned.m16n8k16.row.col.f32.bf16.bf16.f32 "
        "{%0,%1,%2,%3}, {%4,%5,%6,%7}, {%8,%9}, {%0,%1,%2,%3};"
        : "+f"(d[0]), "+f"(d[1]), "+f"(d[2]), "+f"(d[3])
        : "r"(a[0]), "r"(a[1]), "r"(a[2]), "r"(a[3]), "r"(b0), "r"(b1));
}
// conflict-free SW128 swizzle: rows x 128B, 16B chunks
__device__ __forceinline__ uint32_t swz128(uint32_t row, uint32_t chunk) {
    return row * 128u + ((chunk ^ (row & 7u)) * 16u);
}

// ---------------- Kernel 1: rowsum -> d ----------------
__global__ void rowsum_kernel(const float* __restrict__ adj) {
    int row = blockIdx.x;
    const float4* a4 = reinterpret_cast<const float4*>(adj + (size_t)row * N_NODES);
    int t = threadIdx.x;
    float s = 0.f;
#pragma unroll
    for (int i = 0; i < N_NODES / 4 / 256; i++) {
        float4 v = __ldg(&a4[t + i * 256]);
        s += (v.x + v.y) + (v.z + v.w);
    }
#pragma unroll
    for (int o = 16; o; o >>= 1) s += __shfl_xor_sync(0xffffffffu, s, o);
    __shared__ float ws[8];
    if ((t & 31) == 0) ws[t >> 5] = s;
    __syncthreads();
    if (t == 0) {
        float v = 0.f;
#pragma unroll
        for (int w = 0; w < 8; w++) v += ws[w];
        g_d[row] = rsqrtf(v + EPSV);
    }
}

// ---------------- Kernel 2: z1^T (bf16 hi/lo) = (d .* (x @ W1))^T ----------------
// smem-transpose so the transposed gmem writes are coalesced 16B stores.
__global__ void xw1_kernel(const float* __restrict__ x, const float* __restrict__ W1) {
    __shared__ float sW[F_IN * F_HID];     // 32 KB; reused as zbuf[64][65] later
    int t = threadIdx.x;
    for (int i = t; i < F_IN * F_HID; i += 256) sW[i] = W1[i];
    __syncthreads();

    int blockRow = blockIdx.x * 64;
    int nloc = t >> 2;
    int c0   = (t & 3) * 16;
    const float* xr = x + (size_t)(blockRow + nloc) * F_IN;
    float acc[16];
#pragma unroll
    for (int c = 0; c < 16; c++) acc[c] = 0.f;
    for (int k = 0; k < F_IN; k++) {
        float xv = __ldg(xr + k);
#pragma unroll
        for (int c = 0; c < 16; c++) acc[c] += xv * sW[k * F_HID + c0 + c];
    }
    float dv = g_d[blockRow + nloc];
    __syncthreads();                        // done reading sW
    float* zb = sW;                         // zbuf[64][65]
#pragma unroll
    for (int c = 0; c < 16; c++) zb[nloc * 65 + c0 + c] = dv * acc[c];
    __syncthreads();

    // write phase: thread = (feat f, 16-node chunk c)
    int f = t >> 2, c = t & 3;
    uint32_t hi[8], lo[8];
#pragma unroll
    for (int i = 0; i < 8; i++) {
        float z0 = zb[(c * 16 + 2 * i) * 65 + f];
        float z1 = zb[(c * 16 + 2 * i + 1) * 65 + f];
        uint32_t h = pack_bf(z0, z1);
        float r0 = z0 - __uint_as_float(h << 16);
        float r1 = z1 - __uint_as_float(h & 0xffff0000u);
        hi[i] = h;
        lo[i] = pack_bf(r0, r1);
    }
    size_t dst = (size_t)f * N_NODES + blockRow + c * 16;
    uint4* ph = reinterpret_cast<uint4*>(g_z1hiT + dst);
    uint4* pl = reinterpret_cast<uint4*>(g_z1loT + dst);
    ph[0] = make_uint4(hi[0], hi[1], hi[2], hi[3]);
    ph[1] = make_uint4(hi[4], hi[5], hi[6], hi[7]);
    pl[0] = make_uint4(lo[0], lo[1], lo[2], lo[3]);
    pl[1] = make_uint4(lo[4], lo[5], lo[6], lo[7]);
}

// ---------------- Kernel 3: HMMA split-K GEMM: part[s] = A[:, ks] @ z1[ks, :] ----------------
// BM=64, BN=64, KT=64, split-K=2 -> 256 CTAs, 2 CTAs/SM. Swizzled conflict-free smem.
#define KT        64
#define K_SPLIT   (N_NODES / 2)         // 4096
#define NKT       (K_SPLIT / KT)        // 64
#define A_HI      0
#define A_LO      8192
#define B_HI      16384
#define B_LO      24576
#define STAGE_B   32768
#define SMEM_SZ   (2 * STAGE_B)         // 65536

__global__ __launch_bounds__(256, 2)
void agg1_mma_kernel(const float* __restrict__ adj) {
    extern __shared__ __align__(1024) char smem[];
    uint32_t sbase = smem_u32(smem);
    int t = threadIdx.x;
    int wid = t >> 5, lane = t & 31;

    int mtile = blockIdx.x >> 1;
    int split = blockIdx.x & 1;
    int blockRow = mtile * 64;
    int kbase = split * K_SPLIT;

    int warpM = (wid & 1) * 32;         // 0,32
    int warpN = (wid >> 1) * 16;        // 0,16,32,48

    // ldmatrix lane address components
    uint32_t aRowLane = (uint32_t)(lane & 15);
    uint32_t aChunkLane = (uint32_t)(lane >> 4);
    uint32_t bRowLane = (uint32_t)((lane & 7) + ((lane >> 4) & 1) * 8);
    uint32_t bChunkLane = (uint32_t)((lane >> 3) & 1);

    // staging mapping: r = row (A) / n (B), q = chunk group
    int r = t >> 2, q = t & 3;
    const float* aRow = adj + (size_t)(blockRow + r) * N_NODES + kbase + q * 16;
    const __nv_bfloat16* bhRow = g_z1hiT + (size_t)r * N_NODES + kbase;
    const __nv_bfloat16* blRow = g_z1loT + (size_t)r * N_NODES + kbase;

    float4 aReg[4];
    float4 bhReg[2], blReg[2];

    float acc[2][2][4];
#pragma unroll
    for (int mi = 0; mi < 2; mi++)
#pragma unroll
        for (int ni = 0; ni < 2; ni++)
#pragma unroll
            for (int e = 0; e < 4; e++) acc[mi][ni][e] = 0.f;

    auto ldg_tile = [&](int kt) {
        const float4* ap = reinterpret_cast<const float4*>(aRow + kt * KT);
#pragma unroll
        for (int i = 0; i < 4; i++) aReg[i] = __ldg(&ap[i]);
        const float4* bh = reinterpret_cast<const float4*>(bhRow + kt * KT);
        const float4* bl = reinterpret_cast<const float4*>(blRow + kt * KT);
        bhReg[0] = __ldg(&bh[q]);  bhReg[1] = __ldg(&bh[q + 4]);
        blReg[0] = __ldg(&bl[q]);  blReg[1] = __ldg(&bl[q + 4]);
    };
    auto sts_tile = [&](int stage) {
        uint32_t st = sbase + (uint32_t)(stage * STAGE_B);
        // A: 16 floats (4 float4) -> bf16 chunks 2q, 2q+1
        uint32_t hv[8], lv[8];
#pragma unroll
        for (int i = 0; i < 4; i++) {
            uint32_t h01 = pack_bf(aReg[i].x, aReg[i].y);
            uint32_t h23 = pack_bf(aReg[i].z, aReg[i].w);
            float r0 = aReg[i].x - __uint_as_float(h01 << 16);
            float r1 = aReg[i].y - __uint_as_float(h01 & 0xffff0000u);
            float r2 = aReg[i].z - __uint_as_float(h23 << 16);
            float r3 = aReg[i].w - __uint_as_float(h23 & 0xffff0000u);
            hv[2 * i] = h01; hv[2 * i + 1] = h23;
            lv[2 * i] = pack_bf(r0, r1); lv[2 * i + 1] = pack_bf(r2, r3);
        }
        uint32_t ca0 = swz128((uint32_t)r, (uint32_t)(2 * q));
        uint32_t ca1 = swz128((uint32_t)r, (uint32_t)(2 * q + 1));
        asm volatile("st.shared.v4.b32 [%0], {%1,%2,%3,%4};" ::
            "r"(st + A_HI + ca0), "r"(hv[0]), "r"(hv[1]), "r"(hv[2]), "r"(hv[3]));
        asm volatile("st.shared.v4.b32 [%0], {%1,%2,%3,%4};" ::
            "r"(st + A_HI + ca1), "r"(hv[4]), "r"(hv[5]), "r"(hv[6]), "r"(hv[7]));
        asm volatile("st.shared.v4.b32 [%0], {%1,%2,%3,%4};" ::
            "r"(st + A_LO + ca0), "r"(lv[0]), "r"(lv[1]), "r"(lv[2]), "r"(lv[3]));
        asm volatile("st.shared.v4.b32 [%0], {%1,%2,%3,%4};" ::
            "r"(st + A_LO + ca1), "r"(lv[4]), "r"(lv[5]), "r"(lv[6]), "r"(lv[7]));
        // B: chunks q and q+4
        uint32_t cb0 = swz128((uint32_t)r, (uint32_t)q);
        uint32_t cb1 = swz128((uint32_t)r, (uint32_t)(q + 4));
        *reinterpret_cast<float4*>(smem + stage * STAGE_B + B_HI + cb0) = bhReg[0];
        *reinterpret_cast<float4*>(smem + stage * STAGE_B + B_HI + cb1) = bhReg[1];
        *reinterpret_cast<float4*>(smem + stage * STAGE_B + B_LO + cb0) = blReg[0];
        *reinterpret_cast<float4*>(smem + stage * STAGE_B + B_LO + cb1) = blReg[1];
    };

    // prologue
    ldg_tile(0);
    sts_tile(0);
    __syncthreads();

    for (int kt = 0; kt < NKT; kt++) {
        int s = kt & 1;
        bool more = (kt + 1 < NKT);
        if (more) ldg_tile(kt + 1);          // overlaps with MMA below

        uint32_t st = sbase + (uint32_t)(s * STAGE_B);

#pragma unroll
        for (int ks = 0; ks < 4; ks++) {
            uint32_t Ah[2][4], Al[2][4], Bh[4], Bl[4];
#pragma unroll
            for (int mi = 0; mi < 2; mi++) {
                uint32_t row = (uint32_t)(warpM + mi * 16) + aRowLane;
                uint32_t ch  = (uint32_t)(ks * 2) + aChunkLane;
                uint32_t off = swz128(row, ch);
                ldsm_x4(Ah[mi], st + A_HI + off);
                ldsm_x4(Al[mi], st + A_LO + off);
            }
            {
                uint32_t row = (uint32_t)warpN + bRowLane;
                uint32_t ch  = (uint32_t)(ks * 2) + bChunkLane;
                uint32_t off = swz128(row, ch);
                ldsm_x4(Bh, st + B_HI + off);
                ldsm_x4(Bl, st + B_LO + off);
            }
#pragma unroll
            for (int mi = 0; mi < 2; mi++) {
#pragma unroll
                for (int ni = 0; ni < 2; ni++) {
                    mma16816(acc[mi][ni], Ah[mi], Bh[2 * ni], Bh[2 * ni + 1]);
                    mma16816(acc[mi][ni], Ah[mi], Bl[2 * ni], Bl[2 * ni + 1]);
                    mma16816(acc[mi][ni], Al[mi], Bh[2 * ni], Bh[2 * ni + 1]);
                }
            }
        }
        if (more) sts_tile(s ^ 1);
        __syncthreads();
    }

    // epilogue: write split-K partials
    int g = lane >> 2, tig = lane & 3;
    float* base = g_part + (size_t)split * N_NODES * F_HID;
#pragma unroll
    for (int mi = 0; mi < 2; mi++) {
        int row = blockRow + warpM + mi * 16 + g;
#pragma unroll
        for (int ni = 0; ni < 2; ni++) {
            int col = warpN + ni * 8 + tig * 2;
            *reinterpret_cast<float2*>(base + (size_t)row * F_HID + col) =
                make_float2(acc[mi][ni][0], acc[mi][ni][1]);
            *reinterpret_cast<float2*>(base + (size_t)(row + 8) * F_HID + col) =
                make_float2(acc[mi][ni][2], acc[mi][ni][3]);
        }
    }
}

// ---------------- Kernel 4: h = relu(d.*(p0+p1)+b1); z2 = d .* (h @ W2) ----------------
__global__ void hw2_fused_kernel(const float* __restrict__ W2, const float* __restrict__ b1) {
    __shared__ float sW[F_HID * F_OUT];
    __shared__ float sb1[F_HID];
    int t = threadIdx.x;
    if (t < F_HID * F_OUT) sW[t] = W2[t];
    if (t < F_HID) sb1[t] = b1[t];
    __syncthreads();
    int row = blockIdx.x * 256 + t;
    float dv = g_d[row];
    const float4* p0 = reinterpret_cast<const float4*>(g_part + (size_t)row * F_HID);
    const float4* p1 = reinterpret_cast<const float4*>(g_part + ((size_t)N_NODES + row) * F_HID);
    float a0 = 0.f, a1 = 0.f;
#pragma unroll
    for (int i = 0; i < F_HID / 4; i++) {
        float4 u = __ldg(&p0[i]);
        float4 v = __ldg(&p1[i]);
        float h0 = fmaxf(fmaf(dv, u.x + v.x, sb1[4 * i + 0]), 0.f);
        float h1 = fmaxf(fmaf(dv, u.y + v.y, sb1[4 * i + 1]), 0.f);
        float h2 = fmaxf(fmaf(dv, u.z + v.z, sb1[4 * i + 2]), 0.f);
        float h3 = fmaxf(fmaf(dv, u.w + v.w, sb1[4 * i + 3]), 0.f);
        a0 += h0 * sW[(4 * i + 0) * 2] + h1 * sW[(4 * i + 1) * 2]
            + h2 * sW[(4 * i + 2) * 2] + h3 * sW[(4 * i + 3) * 2];
        a1 += h0 * sW[(4 * i + 0) * 2 + 1] + h1 * sW[(4 * i + 1) * 2 + 1]
            + h2 * sW[(4 * i + 2) * 2 + 1] + h3 * sW[(4 * i + 3) * 2 + 1];
    }
    g_z2[2 * row + 0] = dv * a0;
    g_z2[2 * row + 1] = dv * a1;
}

// ---------------- Kernel 5: out = d .* (A @ z2) + b2 ----------------
__global__ void agg2_kernel(const float* __restrict__ adj, const float* __restrict__ b2,
                            float* __restrict__ out) {
    int row = blockIdx.x;
    int t = threadIdx.x;
    const float4* a4 = reinterpret_cast<const float4*>(adj + (size_t)row * N_NODES);
    const float2* z2 = reinterpret_cast<const float2*>(g_z2);
    float a0 = 0.f, a1 = 0.f;
#pragma unroll
    for (int i = 0; i < N_NODES / 4 / 256; i++) {
        int j = t + 256 * i;
        float4 v = __ldg(&a4[j]);
        float2 z0 = __ldg(&z2[4 * j + 0]);
        float2 z1 = __ldg(&z2[4 * j + 1]);
        float2 zz = __ldg(&z2[4 * j + 2]);
        float2 z3 = __ldg(&z2[4 * j + 3]);
        a0 += v.x * z0.x + v.y * z1.x + v.z * zz.x + v.w * z3.x;
        a1 += v.x * z0.y + v.y * z1.y + v.z * zz.y + v.w * z3.y;
    }
#pragma unroll
    for (int o = 16; o; o >>= 1) {
        a0 += __shfl_xor_sync(0xffffffffu, a0, o);
        a1 += __shfl_xor_sync(0xffffffffu, a1, o);
    }
    __shared__ float red[16];
    if ((t & 31) == 0) { red[(t >> 5) * 2] = a0; red[(t >> 5) * 2 + 1] = a1; }
    __syncthreads();
    if (t == 0) {
        float s0 = 0.f, s1 = 0.f;
#pragma unroll
        for (int w = 0; w < 8; w++) { s0 += red[2 * w]; s1 += red[2 * w + 1]; }
        float dv = g_d[row];
        out[2 * row + 0] = fmaf(dv, s0, b2[0]);
        out[2 * row + 1] = fmaf(dv, s1, b2[1]);
    }
}

// ---------------- launch ----------------
extern "C" void kernel_launch(void* const* d_in, const int* in_sizes, int n_in,
                              void* d_out, int out_size) {
    const float* x   = (const float*)d_in[0];
    const float* adj = (const float*)d_in[1];
    const float* W1  = (const float*)d_in[2];
    const float* b1  = (const float*)d_in[3];
    const float* W2  = (const float*)d_in[4];
    const float* b2  = (const float*)d_in[5];
    float* out = (float*)d_out;

    cudaFuncSetAttribute(agg1_mma_kernel,
                         cudaFuncAttributeMaxDynamicSharedMemorySize, SMEM_SZ);

    rowsum_kernel<<<N_NODES, 256>>>(adj);
    xw1_kernel<<<N_NODES / 64, 256>>>(x, W1);
    agg1_mma_kernel<<<2 * (N_NODES / 64), 256, SMEM_SZ>>>(adj);
    hw2_fused_kernel<<<N_NODES / 256, 256>>>(W2, b1);
    agg2_kernel<<<N_NODES, 256>>>(adj, b2, out);
}

// round 11
// speedup vs baseline: 2.1521x; 1.2238x over previous
#include <cuda_runtime.h>
#include <cuda_fp16.h>
#include <cstdint>

#define N_NODES 8192
#define F_IN    128
#define F_HID   64
#define F_OUT   2
#define EPSV    1e-6f

// ---------------- scratch (no allocations allowed) ----------------
__device__ float g_d[N_NODES];                   // 1/sqrt(rowsum+eps)
__device__ __half g_z1T[F_HID * N_NODES];        // (d.*xW1)^T fp16, [64][8192]
__device__ float g_part[2 * N_NODES * F_HID];    // split-K partials of A @ z1
__device__ float g_z2[N_NODES * F_OUT];          // d .* (h @ W2)

// ================= helpers =================
__device__ __forceinline__ uint32_t smem_u32(const void* p) {
    uint32_t a;
    asm("{ .reg .u64 t; cvta.to.shared.u64 t, %1; cvt.u32.u64 %0, t; }" : "=r"(a) : "l"(p));
    return a;
}
// pack two fp32 -> f16x2, f0 in low half (first k element)
__device__ __forceinline__ uint32_t pack_f16(float f0, float f1) {
    uint32_t r;
    asm("cvt.rn.f16x2.f32 %0, %1, %2;" : "=r"(r) : "f"(f1), "f"(f0));
    return r;
}
__device__ __forceinline__ void ldsm_x4(uint32_t* r, uint32_t addr) {
    asm volatile("ldmatrix.sync.aligned.m8n8.x4.shared.b16 {%0,%1,%2,%3}, [%4];"
                 : "=r"(r[0]), "=r"(r[1]), "=r"(r[2]), "=r"(r[3]) : "r"(addr));
}
__device__ __forceinline__ void mma16816(float* d, const uint32_t* a,
                                         uint32_t b0, uint32_t b1) {
    asm volatile(
        "mma.sync.aligned.m16n8k16.row.col.f32.f16.f16.f32 "
        "{%0,%1,%2,%3}, {%4,%5,%6,%7}, {%8,%9}, {%0,%1,%2,%3};"
        : "+f"(d[0]), "+f"(d[1]), "+f"(d[2]), "+f"(d[3])
        : "r"(a[0]), "r"(a[1]), "r"(a[2]), "r"(a[3]), "r"(b0), "r"(b1));
}
// conflict-free swizzle: rows x 128B, 16B chunks
__device__ __forceinline__ uint32_t swz128(uint32_t row, uint32_t chunk) {
    return row * 128u + ((chunk ^ (row & 7u)) * 16u);
}

// ---------------- Kernel 1: rowsum -> d ----------------
__global__ void rowsum_kernel(const float* __restrict__ adj) {
    int row = blockIdx.x;
    const float4* a4 = reinterpret_cast<const float4*>(adj + (size_t)row * N_NODES);
    int t = threadIdx.x;
    float s = 0.f;
#pragma unroll
    for (int i = 0; i < N_NODES / 4 / 256; i++) {
        float4 v = __ldg(&a4[t + i * 256]);
        s += (v.x + v.y) + (v.z + v.w);
    }
#pragma unroll
    for (int o = 16; o; o >>= 1) s += __shfl_xor_sync(0xffffffffu, s, o);
    __shared__ float ws[8];
    if ((t & 31) == 0) ws[t >> 5] = s;
    __syncthreads();
    if (t == 0) {
        float v = 0.f;
#pragma unroll
        for (int w = 0; w < 8; w++) v += ws[w];
        g_d[row] = rsqrtf(v + EPSV);
    }
}

// ---------------- Kernel 2: z1^T (fp16) = (d .* (x @ W1))^T ----------------
// smem-transpose so the transposed gmem writes are coalesced 16B stores.
__global__ void xw1_kernel(const float* __restrict__ x, const float* __restrict__ W1) {
    __shared__ float sW[F_IN * F_HID];     // 32 KB; reused as zbuf[64][65] later
    int t = threadIdx.x;
    for (int i = t; i < F_IN * F_HID; i += 256) sW[i] = W1[i];
    __syncthreads();

    int blockRow = blockIdx.x * 64;
    int nloc = t >> 2;
    int c0   = (t & 3) * 16;
    const float* xr = x + (size_t)(blockRow + nloc) * F_IN;
    float acc[16];
#pragma unroll
    for (int c = 0; c < 16; c++) acc[c] = 0.f;
    for (int k = 0; k < F_IN; k++) {
        float xv = __ldg(xr + k);
#pragma unroll
        for (int c = 0; c < 16; c++) acc[c] += xv * sW[k * F_HID + c0 + c];
    }
    float dv = g_d[blockRow + nloc];
    __syncthreads();                        // done reading sW
    float* zb = sW;                         // zbuf[64][65]
#pragma unroll
    for (int c = 0; c < 16; c++) zb[nloc * 65 + c0 + c] = dv * acc[c];
    __syncthreads();

    // write phase: thread = (feat f, 16-node chunk c)
    int f = t >> 2, c = t & 3;
    uint32_t hv[8];
#pragma unroll
    for (int i = 0; i < 8; i++) {
        float z0 = zb[(c * 16 + 2 * i) * 65 + f];
        float z1 = zb[(c * 16 + 2 * i + 1) * 65 + f];
        hv[i] = pack_f16(z0, z1);
    }
    size_t dst = (size_t)f * N_NODES + blockRow + c * 16;
    uint4* ph = reinterpret_cast<uint4*>(g_z1T + dst);
    ph[0] = make_uint4(hv[0], hv[1], hv[2], hv[3]);
    ph[1] = make_uint4(hv[4], hv[5], hv[6], hv[7]);
}

// ---------------- Kernel 3: HMMA split-K GEMM (fp16 single product) ----------------
// BM=64, BN=64, KT=64, split-K=2 -> 256 CTAs, 2 CTAs/SM. Swizzled conflict-free smem.
#define KT        64
#define K_SPLIT   (N_NODES / 2)         // 4096
#define NKT       (K_SPLIT / KT)        // 64
#define A_OFF     0
#define B_OFF     8192
#define STAGE_B   16384
#define SMEM_SZ   (2 * STAGE_B)         // 32768

__global__ __launch_bounds__(256, 2)
void agg1_mma_kernel(const float* __restrict__ adj) {
    extern __shared__ __align__(1024) char smem[];
    uint32_t sbase = smem_u32(smem);
    int t = threadIdx.x;
    int wid = t >> 5, lane = t & 31;

    int mtile = blockIdx.x >> 1;
    int split = blockIdx.x & 1;
    int blockRow = mtile * 64;
    int kbase = split * K_SPLIT;

    int warpM = (wid & 1) * 32;         // 0,32
    int warpN = (wid >> 1) * 16;        // 0,16,32,48

    // ldmatrix lane address components
    uint32_t aRowLane = (uint32_t)(lane & 15);
    uint32_t aChunkLane = (uint32_t)(lane >> 4);
    uint32_t bRowLane = (uint32_t)((lane & 7) + ((lane >> 4) & 1) * 8);
    uint32_t bChunkLane = (uint32_t)((lane >> 3) & 1);

    // staging mapping: r = row (A) / n (B), q = chunk group
    int r = t >> 2, q = t & 3;
    const float* aRow = adj + (size_t)(blockRow + r) * N_NODES + kbase + q * 16;
    const __half* bRow = g_z1T + (size_t)r * N_NODES + kbase;

    float4 aReg[4];
    float4 bReg[2];

    float acc[2][2][4];
#pragma unroll
    for (int mi = 0; mi < 2; mi++)
#pragma unroll
        for (int ni = 0; ni < 2; ni++)
#pragma unroll
            for (int e = 0; e < 4; e++) acc[mi][ni][e] = 0.f;

    auto ldg_tile = [&](int kt) {
        const float4* ap = reinterpret_cast<const float4*>(aRow + kt * KT);
#pragma unroll
        for (int i = 0; i < 4; i++) aReg[i] = __ldg(&ap[i]);
        const float4* bp = reinterpret_cast<const float4*>(bRow + kt * KT);
        bReg[0] = __ldg(&bp[q]);  bReg[1] = __ldg(&bp[q + 4]);
    };
    auto sts_tile = [&](int stage) {
        uint32_t st = sbase + (uint32_t)(stage * STAGE_B);
        // A: 16 floats (4 float4) -> fp16 chunks 2q, 2q+1
        uint32_t hv[8];
#pragma unroll
        for (int i = 0; i < 4; i++) {
            hv[2 * i]     = pack_f16(aReg[i].x, aReg[i].y);
            hv[2 * i + 1] = pack_f16(aReg[i].z, aReg[i].w);
        }
        uint32_t ca0 = swz128((uint32_t)r, (uint32_t)(2 * q));
        uint32_t ca1 = swz128((uint32_t)r, (uint32_t)(2 * q + 1));
        asm volatile("st.shared.v4.b32 [%0], {%1,%2,%3,%4};" ::
            "r"(st + A_OFF + ca0), "r"(hv[0]), "r"(hv[1]), "r"(hv[2]), "r"(hv[3]));
        asm volatile("st.shared.v4.b32 [%0], {%1,%2,%3,%4};" ::
            "r"(st + A_OFF + ca1), "r"(hv[4]), "r"(hv[5]), "r"(hv[6]), "r"(hv[7]));
        // B: chunks q and q+4 (already fp16)
        uint32_t cb0 = swz128((uint32_t)r, (uint32_t)q);
        uint32_t cb1 = swz128((uint32_t)r, (uint32_t)(q + 4));
        *reinterpret_cast<float4*>(smem + stage * STAGE_B + B_OFF + cb0) = bReg[0];
        *reinterpret_cast<float4*>(smem + stage * STAGE_B + B_OFF + cb1) = bReg[1];
    };

    // prologue
    ldg_tile(0);
    sts_tile(0);
    __syncthreads();

    for (int kt = 0; kt < NKT; kt++) {
        int s = kt & 1;
        bool more = (kt + 1 < NKT);
        if (more) ldg_tile(kt + 1);          // overlaps with MMA below

        uint32_t st = sbase + (uint32_t)(s * STAGE_B);

#pragma unroll
        for (int ks = 0; ks < 4; ks++) {
            uint32_t Am[2][4], Bm[4];
#pragma unroll
            for (int mi = 0; mi < 2; mi++) {
                uint32_t row = (uint32_t)(warpM + mi * 16) + aRowLane;
                uint32_t ch  = (uint32_t)(ks * 2) + aChunkLane;
                ldsm_x4(Am[mi], st + A_OFF + swz128(row, ch));
            }
            {
                uint32_t row = (uint32_t)warpN + bRowLane;
                uint32_t ch  = (uint32_t)(ks * 2) + bChunkLane;
                ldsm_x4(Bm, st + B_OFF + swz128(row, ch));
            }
#pragma unroll
            for (int mi = 0; mi < 2; mi++)
#pragma unroll
                for (int ni = 0; ni < 2; ni++)
                    mma16816(acc[mi][ni], Am[mi], Bm[2 * ni], Bm[2 * ni + 1]);
        }
        if (more) sts_tile(s ^ 1);
        __syncthreads();
    }

    // epilogue: write split-K partials
    int g = lane >> 2, tig = lane & 3;
    float* base = g_part + (size_t)split * N_NODES * F_HID;
#pragma unroll
    for (int mi = 0; mi < 2; mi++) {
        int row = blockRow + warpM + mi * 16 + g;
#pragma unroll
        for (int ni = 0; ni < 2; ni++) {
            int col = warpN + ni * 8 + tig * 2;
            *reinterpret_cast<float2*>(base + (size_t)row * F_HID + col) =
                make_float2(acc[mi][ni][0], acc[mi][ni][1]);
            *reinterpret_cast<float2*>(base + (size_t)(row + 8) * F_HID + col) =
                make_float2(acc[mi][ni][2], acc[mi][ni][3]);
        }
    }
}

// ---------------- Kernel 4: h = relu(d.*(p0+p1)+b1); z2 = d .* (h @ W2) ----------------
__global__ void hw2_fused_kernel(const float* __restrict__ W2, const float* __restrict__ b1) {
    __shared__ float sW[F_HID * F_OUT];
    __shared__ float sb1[F_HID];
    int t = threadIdx.x;
    if (t < F_HID * F_OUT) sW[t] = W2[t];
    if (t < F_HID) sb1[t] = b1[t];
    __syncthreads();
    int row = blockIdx.x * 256 + t;
    float dv = g_d[row];
    const float4* p0 = reinterpret_cast<const float4*>(g_part + (size_t)row * F_HID);
    const float4* p1 = reinterpret_cast<const float4*>(g_part + ((size_t)N_NODES + row) * F_HID);
    float a0 = 0.f, a1 = 0.f;
#pragma unroll
    for (int i = 0; i < F_HID / 4; i++) {
        float4 u = __ldg(&p0[i]);
        float4 v = __ldg(&p1[i]);
        float h0 = fmaxf(fmaf(dv, u.x + v.x, sb1[4 * i + 0]), 0.f);
        float h1 = fmaxf(fmaf(dv, u.y + v.y, sb1[4 * i + 1]), 0.f);
        float h2 = fmaxf(fmaf(dv, u.z + v.z, sb1[4 * i + 2]), 0.f);
        float h3 = fmaxf(fmaf(dv, u.w + v.w, sb1[4 * i + 3]), 0.f);
        a0 += h0 * sW[(4 * i + 0) * 2] + h1 * sW[(4 * i + 1) * 2]
            + h2 * sW[(4 * i + 2) * 2] + h3 * sW[(4 * i + 3) * 2];
        a1 += h0 * sW[(4 * i + 0) * 2 + 1] + h1 * sW[(4 * i + 1) * 2 + 1]
            + h2 * sW[(4 * i + 2) * 2 + 1] + h3 * sW[(4 * i + 3) * 2 + 1];
    }
    g_z2[2 * row + 0] = dv * a0;
    g_z2[2 * row + 1] = dv * a1;
}

// ---------------- Kernel 5: out = d .* (A @ z2) + b2 ----------------
__global__ void agg2_kernel(const float* __restrict__ adj, const float* __restrict__ b2,
                            float* __restrict__ out) {
    int row = blockIdx.x;
    int t = threadIdx.x;
    const float4* a4 = reinterpret_cast<const float4*>(adj + (size_t)row * N_NODES);
    const float2* z2 = reinterpret_cast<const float2*>(g_z2);
    float a0 = 0.f, a1 = 0.f;
#pragma unroll
    for (int i = 0; i < N_NODES / 4 / 256; i++) {
        int j = t + 256 * i;
        float4 v = __ldg(&a4[j]);
        float2 z0 = __ldg(&z2[4 * j + 0]);
        float2 z1 = __ldg(&z2[4 * j + 1]);
        float2 zz = __ldg(&z2[4 * j + 2]);
        float2 z3 = __ldg(&z2[4 * j + 3]);
        a0 += v.x * z0.x + v.y * z1.x + v.z * zz.x + v.w * z3.x;
        a1 += v.x * z0.y + v.y * z1.y + v.z * zz.y + v.w * z3.y;
    }
#pragma unroll
    for (int o = 16; o; o >>= 1) {
        a0 += __shfl_xor_sync(0xffffffffu, a0, o);
        a1 += __shfl_xor_sync(0xffffffffu, a1, o);
    }
    __shared__ float red[16];
    if ((t & 31) == 0) { red[(t >> 5) * 2] = a0; red[(t >> 5) * 2 + 1] = a1; }
    __syncthreads();
    if (t == 0) {
        float s0 = 0.f, s1 = 0.f;
#pragma unroll
        for (int w = 0; w < 8; w++) { s0 += red[2 * w]; s1 += red[2 * w + 1]; }
        float dv = g_d[row];
        out[2 * row + 0] = fmaf(dv, s0, b2[0]);
        out[2 * row + 1] = fmaf(dv, s1, b2[1]);
    }
}

// ---------------- launch ----------------
extern "C" void kernel_launch(void* const* d_in, const int* in_sizes, int n_in,
                              void* d_out, int out_size) {
    const float* x   = (const float*)d_in[0];
    const float* adj = (const float*)d_in[1];
    const float* W1  = (const float*)d_in[2];
    const float* b1  = (const float*)d_in[3];
    const float* W2  = (const float*)d_in[4];
    const float* b2  = (const float*)d_in[5];
    float* out = (float*)d_out;

    cudaFuncSetAttribute(agg1_mma_kernel,
                         cudaFuncAttributeMaxDynamicSharedMemorySize, SMEM_SZ);

    rowsum_kernel<<<N_NODES, 256>>>(adj);
    xw1_kernel<<<N_NODES / 64, 256>>>(x, W1);
    agg1_mma_kernel<<<2 * (N_NODES / 64), 256, SMEM_SZ>>>(adj);
    hw2_fused_kernel<<<N_NODES / 256, 256>>>(W2, b1);
    agg2_kernel<<<N_NODES, 256>>>(adj, b2, out);
}

// round 12
// speedup vs baseline: 2.2144x; 1.0289x over previous
#include <cuda_runtime.h>
#include <cuda_fp16.h>
#include <cstdint>

#define N_NODES 8192
#define F_IN    128
#define F_HID   64
#define F_OUT   2
#define EPSV    1e-6f

// ---------------- scratch (no allocations allowed) ----------------
__device__ float g_d[N_NODES];                       // 1/sqrt(rowsum+eps)
__device__ __half g_adj16[(size_t)N_NODES * N_NODES]; // adj rounded to fp16 (128 MB)
__device__ __half g_z1T[F_HID * N_NODES];            // (d.*xW1)^T fp16, [64][8192]
__device__ float g_part[2 * N_NODES * F_HID];        // split-K partials of A @ z1
__device__ float g_z2[N_NODES * F_OUT];              // d .* (h @ W2)

// ================= helpers =================
__device__ __forceinline__ uint32_t smem_u32(const void* p) {
    uint32_t a;
    asm("{ .reg .u64 t; cvta.to.shared.u64 t, %1; cvt.u32.u64 %0, t; }" : "=r"(a) : "l"(p));
    return a;
}
// pack two fp32 -> f16x2, f0 in low half (first k element)
__device__ __forceinline__ uint32_t pack_f16(float f0, float f1) {
    uint32_t r;
    asm("cvt.rn.f16x2.f32 %0, %1, %2;" : "=r"(r) : "f"(f1), "f"(f0));
    return r;
}
__device__ __forceinline__ void ldsm_x4(uint32_t* r, uint32_t addr) {
    asm volatile("ldmatrix.sync.aligned.m8n8.x4.shared.b16 {%0,%1,%2,%3}, [%4];"
                 : "=r"(r[0]), "=r"(r[1]), "=r"(r[2]), "=r"(r[3]) : "r"(addr));
}
__device__ __forceinline__ void mma16816(float* d, const uint32_t* a,
                                         uint32_t b0, uint32_t b1) {
    asm volatile(
        "mma.sync.aligned.m16n8k16.row.col.f32.f16.f16.f32 "
        "{%0,%1,%2,%3}, {%4,%5,%6,%7}, {%8,%9}, {%0,%1,%2,%3};"
        : "+f"(d[0]), "+f"(d[1]), "+f"(d[2]), "+f"(d[3])
        : "r"(a[0]), "r"(a[1]), "r"(a[2]), "r"(a[3]), "r"(b0), "r"(b1));
}
// conflict-free swizzle: rows x 128B, 16B chunks
__device__ __forceinline__ uint32_t swz128(uint32_t row, uint32_t chunk) {
    return row * 128u + ((chunk ^ (row & 7u)) * 16u);
}

// ---------------- Kernel 1: rowsum -> d, and adj -> fp16 ----------------
__global__ void rowsum_cvt_kernel(const float* __restrict__ adj) {
    int row = blockIdx.x;
    const float4* a4 = reinterpret_cast<const float4*>(adj + (size_t)row * N_NODES);
    uint2* o2 = reinterpret_cast<uint2*>(g_adj16 + (size_t)row * N_NODES);
    int t = threadIdx.x;
    float s = 0.f;
#pragma unroll
    for (int i = 0; i < N_NODES / 4 / 256; i++) {     // 8 iters
        int j = t + i * 256;
        float4 v = __ldg(&a4[j]);
        s += (v.x + v.y) + (v.z + v.w);
        o2[j] = make_uint2(pack_f16(v.x, v.y), pack_f16(v.z, v.w));
    }
#pragma unroll
    for (int o = 16; o; o >>= 1) s += __shfl_xor_sync(0xffffffffu, s, o);
    __shared__ float ws[8];
    if ((t & 31) == 0) ws[t >> 5] = s;
    __syncthreads();
    if (t == 0) {
        float v = 0.f;
#pragma unroll
        for (int w = 0; w < 8; w++) v += ws[w];
        g_d[row] = rsqrtf(v + EPSV);
    }
}

// ---------------- Kernel 2: z1^T (fp16) = (d .* (x @ W1))^T ----------------
__global__ void xw1_kernel(const float* __restrict__ x, const float* __restrict__ W1) {
    __shared__ float sW[F_IN * F_HID];     // 32 KB; reused as zbuf[64][65] later
    int t = threadIdx.x;
    for (int i = t; i < F_IN * F_HID; i += 256) sW[i] = W1[i];
    __syncthreads();

    int blockRow = blockIdx.x * 64;
    int nloc = t >> 2;
    int c0   = (t & 3) * 16;
    const float* xr = x + (size_t)(blockRow + nloc) * F_IN;
    float acc[16];
#pragma unroll
    for (int c = 0; c < 16; c++) acc[c] = 0.f;
    for (int k = 0; k < F_IN; k++) {
        float xv = __ldg(xr + k);
#pragma unroll
        for (int c = 0; c < 16; c++) acc[c] += xv * sW[k * F_HID + c0 + c];
    }
    float dv = g_d[blockRow + nloc];
    __syncthreads();                        // done reading sW
    float* zb = sW;                         // zbuf[64][65]
#pragma unroll
    for (int c = 0; c < 16; c++) zb[nloc * 65 + c0 + c] = dv * acc[c];
    __syncthreads();

    int f = t >> 2, c = t & 3;
    uint32_t hv[8];
#pragma unroll
    for (int i = 0; i < 8; i++) {
        float z0 = zb[(c * 16 + 2 * i) * 65 + f];
        float z1 = zb[(c * 16 + 2 * i + 1) * 65 + f];
        hv[i] = pack_f16(z0, z1);
    }
    size_t dst = (size_t)f * N_NODES + blockRow + c * 16;
    uint4* ph = reinterpret_cast<uint4*>(g_z1T + dst);
    ph[0] = make_uint4(hv[0], hv[1], hv[2], hv[3]);
    ph[1] = make_uint4(hv[4], hv[5], hv[6], hv[7]);
}

// ---------------- Kernel 3: HMMA split-K GEMM (fp16, pre-converted adj) ----------------
// BM=64, BN=64, KT=64, split-K=2 -> 256 CTAs, 2 CTAs/SM. Swizzled conflict-free smem.
#define KT        64
#define K_SPLIT   (N_NODES / 2)         // 4096
#define NKT       (K_SPLIT / KT)        // 64
#define A_OFF     0
#define B_OFF     8192
#define STAGE_B   16384
#define SMEM_SZ   (2 * STAGE_B)         // 32768

__global__ __launch_bounds__(256, 2)
void agg1_mma_kernel() {
    extern __shared__ __align__(1024) char smem[];
    uint32_t sbase = smem_u32(smem);
    int t = threadIdx.x;
    int wid = t >> 5, lane = t & 31;

    int mtile = blockIdx.x >> 1;
    int split = blockIdx.x & 1;
    int blockRow = mtile * 64;
    int kbase = split * K_SPLIT;

    int warpM = (wid & 1) * 32;         // 0,32
    int warpN = (wid >> 1) * 16;        // 0,16,32,48

    uint32_t aRowLane = (uint32_t)(lane & 15);
    uint32_t aChunkLane = (uint32_t)(lane >> 4);
    uint32_t bRowLane = (uint32_t)((lane & 7) + ((lane >> 4) & 1) * 8);
    uint32_t bChunkLane = (uint32_t)((lane >> 3) & 1);

    // staging mapping: r = row, q = chunk (both A and B rows are 8 x 16B chunks)
    int r = t >> 2, q = t & 3;
    const __half* aRow = g_adj16 + (size_t)(blockRow + r) * N_NODES + kbase;
    const __half* bRow = g_z1T + (size_t)r * N_NODES + kbase;

    uint4 aReg[2], bReg[2];

    float acc[2][2][4];
#pragma unroll
    for (int mi = 0; mi < 2; mi++)
#pragma unroll
        for (int ni = 0; ni < 2; ni++)
#pragma unroll
            for (int e = 0; e < 4; e++) acc[mi][ni][e] = 0.f;

    auto ldg_tile = [&](int kt) {
        const uint4* ap = reinterpret_cast<const uint4*>(aRow + kt * KT);
        const uint4* bp = reinterpret_cast<const uint4*>(bRow + kt * KT);
        aReg[0] = __ldg(&ap[q]);  aReg[1] = __ldg(&ap[q + 4]);
        bReg[0] = __ldg(&bp[q]);  bReg[1] = __ldg(&bp[q + 4]);
    };
    auto sts_tile = [&](int stage) {
        uint32_t st = sbase + (uint32_t)(stage * STAGE_B);
        uint32_t c0 = swz128((uint32_t)r, (uint32_t)q);
        uint32_t c1 = swz128((uint32_t)r, (uint32_t)(q + 4));
        asm volatile("st.shared.v4.b32 [%0], {%1,%2,%3,%4};" ::
            "r"(st + A_OFF + c0), "r"(aReg[0].x), "r"(aReg[0].y), "r"(aReg[0].z), "r"(aReg[0].w));
        asm volatile("st.shared.v4.b32 [%0], {%1,%2,%3,%4};" ::
            "r"(st + A_OFF + c1), "r"(aReg[1].x), "r"(aReg[1].y), "r"(aReg[1].z), "r"(aReg[1].w));
        asm volatile("st.shared.v4.b32 [%0], {%1,%2,%3,%4};" ::
            "r"(st + B_OFF + c0), "r"(bReg[0].x), "r"(bReg[0].y), "r"(bReg[0].z), "r"(bReg[0].w));
        asm volatile("st.shared.v4.b32 [%0], {%1,%2,%3,%4};" ::
            "r"(st + B_OFF + c1), "r"(bReg[1].x), "r"(bReg[1].y), "r"(bReg[1].z), "r"(bReg[1].w));
    };

    // prologue
    ldg_tile(0);
    sts_tile(0);
    __syncthreads();

    for (int kt = 0; kt < NKT; kt++) {
        int s = kt & 1;
        bool more = (kt + 1 < NKT);
        if (more) ldg_tile(kt + 1);          // overlaps with MMA below

        uint32_t st = sbase + (uint32_t)(s * STAGE_B);

#pragma unroll
        for (int ks = 0; ks < 4; ks++) {
            uint32_t Am[2][4], Bm[4];
#pragma unroll
            for (int mi = 0; mi < 2; mi++) {
                uint32_t row = (uint32_t)(warpM + mi * 16) + aRowLane;
                uint32_t ch  = (uint32_t)(ks * 2) + aChunkLane;
                ldsm_x4(Am[mi], st + A_OFF + swz128(row, ch));
            }
            {
                uint32_t row = (uint32_t)warpN + bRowLane;
                uint32_t ch  = (uint32_t)(ks * 2) + bChunkLane;
                ldsm_x4(Bm, st + B_OFF + swz128(row, ch));
            }
#pragma unroll
            for (int mi = 0; mi < 2; mi++)
#pragma unroll
                for (int ni = 0; ni < 2; ni++)
                    mma16816(acc[mi][ni], Am[mi], Bm[2 * ni], Bm[2 * ni + 1]);
        }
        if (more) sts_tile(s ^ 1);
        __syncthreads();
    }

    // epilogue: write split-K partials
    int g = lane >> 2, tig = lane & 3;
    float* base = g_part + (size_t)split * N_NODES * F_HID;
#pragma unroll
    for (int mi = 0; mi < 2; mi++) {
        int row = blockRow + warpM + mi * 16 + g;
#pragma unroll
        for (int ni = 0; ni < 2; ni++) {
            int col = warpN + ni * 8 + tig * 2;
            *reinterpret_cast<float2*>(base + (size_t)row * F_HID + col) =
                make_float2(acc[mi][ni][0], acc[mi][ni][1]);
            *reinterpret_cast<float2*>(base + (size_t)(row + 8) * F_HID + col) =
                make_float2(acc[mi][ni][2], acc[mi][ni][3]);
        }
    }
}

// ---------------- Kernel 4: h = relu(d.*(p0+p1)+b1); z2 = d .* (h @ W2) ----------------
__global__ void hw2_fused_kernel(const float* __restrict__ W2, const float* __restrict__ b1) {
    __shared__ float sW[F_HID * F_OUT];
    __shared__ float sb1[F_HID];
    int t = threadIdx.x;
    if (t < F_HID * F_OUT) sW[t] = W2[t];
    if (t < F_HID) sb1[t] = b1[t];
    __syncthreads();
    int row = blockIdx.x * 256 + t;
    float dv = g_d[row];
    const float4* p0 = reinterpret_cast<const float4*>(g_part + (size_t)row * F_HID);
    const float4* p1 = reinterpret_cast<const float4*>(g_part + ((size_t)N_NODES + row) * F_HID);
    float a0 = 0.f, a1 = 0.f;
#pragma unroll
    for (int i = 0; i < F_HID / 4; i++) {
        float4 u = __ldg(&p0[i]);
        float4 v = __ldg(&p1[i]);
        float h0 = fmaxf(fmaf(dv, u.x + v.x, sb1[4 * i + 0]), 0.f);
        float h1 = fmaxf(fmaf(dv, u.y + v.y, sb1[4 * i + 1]), 0.f);
        float h2 = fmaxf(fmaf(dv, u.z + v.z, sb1[4 * i + 2]), 0.f);
        float h3 = fmaxf(fmaf(dv, u.w + v.w, sb1[4 * i + 3]), 0.f);
        a0 += h0 * sW[(4 * i + 0) * 2] + h1 * sW[(4 * i + 1) * 2]
            + h2 * sW[(4 * i + 2) * 2] + h3 * sW[(4 * i + 3) * 2];
        a1 += h0 * sW[(4 * i + 0) * 2 + 1] + h1 * sW[(4 * i + 1) * 2 + 1]
            + h2 * sW[(4 * i + 2) * 2 + 1] + h3 * sW[(4 * i + 3) * 2 + 1];
    }
    g_z2[2 * row + 0] = dv * a0;
    g_z2[2 * row + 1] = dv * a1;
}

// ---------------- Kernel 5: out = d .* (A @ z2) + b2  (fp16 adj, 8 rows/CTA) ----------------
// z2 (64 KB) staged once per CTA into smem; warp w handles row base+w.
__global__ __launch_bounds__(256, 2)
void agg2_kernel(const float* __restrict__ b2, float* __restrict__ out) {
    extern __shared__ __align__(16) float sz2[];     // 8192 float2 = 64 KB
    int t = threadIdx.x;
    // cooperative load of z2 into smem (4096 float4)
    {
        const float4* zg = reinterpret_cast<const float4*>(g_z2);
        float4* zs = reinterpret_cast<float4*>(sz2);
#pragma unroll
        for (int i = 0; i < 16; i++) zs[t + 256 * i] = __ldg(&zg[t + 256 * i]);
    }
    __syncthreads();

    int wid = t >> 5, lane = t & 31;
    int row = blockIdx.x * 8 + wid;
    const uint4* arow = reinterpret_cast<const uint4*>(g_adj16 + (size_t)row * N_NODES);
    float a0 = 0.f, a1 = 0.f;
#pragma unroll
    for (int it = 0; it < N_NODES / (32 * 8); it++) {   // 32 iters
        int j8 = lane + 32 * it;                        // 8-element group
        uint4 av = __ldg(&arow[j8]);
        const float4* zp = reinterpret_cast<const float4*>(sz2) + j8 * 4;
        float4 z0 = zp[0], z1 = zp[1], z2v = zp[2], z3 = zp[3];
        float2 p0 = __half22float2(*reinterpret_cast<__half2*>(&av.x));
        float2 p1 = __half22float2(*reinterpret_cast<__half2*>(&av.y));
        float2 p2 = __half22float2(*reinterpret_cast<__half2*>(&av.z));
        float2 p3 = __half22float2(*reinterpret_cast<__half2*>(&av.w));
        a0 += p0.x * z0.x + p0.y * z0.z + p1.x * z1.x + p1.y * z1.z
            + p2.x * z2v.x + p2.y * z2v.z + p3.x * z3.x + p3.y * z3.z;
        a1 += p0.x * z0.y + p0.y * z0.w + p1.x * z1.y + p1.y * z1.w
            + p2.x * z2v.y + p2.y * z2v.w + p3.x * z3.y + p3.y * z3.w;
    }
#pragma unroll
    for (int o = 16; o; o >>= 1) {
        a0 += __shfl_xor_sync(0xffffffffu, a0, o);
        a1 += __shfl_xor_sync(0xffffffffu, a1, o);
    }
    if (lane == 0) {
        float dv = g_d[row];
        out[2 * row + 0] = fmaf(dv, a0, __ldg(&b2[0]));
        out[2 * row + 1] = fmaf(dv, a1, __ldg(&b2[1]));
    }
}

// ---------------- launch ----------------
extern "C" void kernel_launch(void* const* d_in, const int* in_sizes, int n_in,
                              void* d_out, int out_size) {
    const float* x   = (const float*)d_in[0];
    const float* adj = (const float*)d_in[1];
    const float* W1  = (const float*)d_in[2];
    const float* b1  = (const float*)d_in[3];
    const float* W2  = (const float*)d_in[4];
    const float* b2  = (const float*)d_in[5];
    float* out = (float*)d_out;

    cudaFuncSetAttribute(agg1_mma_kernel,
                         cudaFuncAttributeMaxDynamicSharedMemorySize, SMEM_SZ);
    cudaFuncSetAttribute(agg2_kernel,
                         cudaFuncAttributeMaxDynamicSharedMemorySize, 65536);

    rowsum_cvt_kernel<<<N_NODES, 256>>>(adj);
    xw1_kernel<<<N_NODES / 64, 256>>>(x, W1);
    agg1_mma_kernel<<<2 * (N_NODES / 64), 256, SMEM_SZ>>>();
    hw2_fused_kernel<<<N_NODES / 256, 256>>>(W2, b1);
    agg2_kernel<<<N_NODES / 8, 256, 65536>>>(b2, out);
}